// round 6
// baseline (speedup 1.0000x reference)
#include <cuda_runtime.h>
#include <cuda_bf16.h>
#include <cstdint>

// Sobel conv (cross-correlation, SAME zero padding) + sign-difference maps.
// Rolling-register design, OPT=2: each lane owns 2 consecutive cols (float2),
// each warp a 64-col strip x RS output rows. No smem, no barriers.
// Column halo via shuffles + predicated edge loads; 3-row separable window.

#define IMG_W 1024
#define IMG_H 1024
#define RS 16            // output rows per warp
#define NWARP 8          // warps per block
#define NT (NWARP * 32)
#define SW 64            // strip width = 32 lanes * 2 cols

__device__ __forceinline__ float fsign(float v) {
    return (float)((v > 0.0f) - (v < 0.0f));
}

__global__ __launch_bounds__(NT, 6)
void sobel_sign_kernel(const float* __restrict__ x,
                       float* __restrict__ y,
                       float* __restrict__ y0,
                       float* __restrict__ y1) {
    const int lane = threadIdx.x & 31;
    const int wid  = threadIdx.x >> 5;
    const int b    = blockIdx.z;
    const int w0   = blockIdx.x * SW;                   // strip base col
    const int r0   = (blockIdx.y * NWARP + wid) * RS;   // first output row
    const int wb   = w0 + lane * 2;                     // lane base col

    const float* __restrict__ xb = x + (size_t)b * IMG_H * IMG_W;
    float* __restrict__ ybx = y + (size_t)b * 2 * IMG_H * IMG_W;
    float* __restrict__ yby = ybx + (size_t)IMG_H * IMG_W;
    const size_t obase = (size_t)b * (size_t)(IMG_H - 1) * (IMG_W - 1);

    const bool lane0  = (lane == 0);
    const bool lane31 = (lane == 31);
    const bool has_l  = (w0 > 0);
    const bool has_r  = (w0 + SW < IMG_W);
    // y0/y1 cols run 0..1022; col wb is always <=1022, col wb+1 needs a guard
    const bool emit1  = (wb + 1 < IMG_W - 1);

    // rolling 3-row window per owned col:
    //   hd[k] = x[c-1] - x[c+1],  hs[k] = x[c-1] + 2 x[c] + x[c+1]
    // hdR: hd for col w0+SW (lane31 only, feeds y0 neighbor sign at strip edge)
    float hdP1x = 0.f, hdP1y = 0.f, hdP2x = 0.f, hdP2y = 0.f;
    float hsP1x = 0.f, hsP1y = 0.f, hsP2x = 0.f, hsP2y = 0.f;
    float hdRP1 = 0.f, hdRP2 = 0.f;
    float sgyPx = 0.f, sgyPy = 0.f;

    #pragma unroll
    for (int i = 0; i < RS + 3; i++) {
        const int j = r0 - 1 + i;                 // input row for this step

        float2 v = make_float2(0.f, 0.f);
        float lf = 0.f, rt1 = 0.f, rt2 = 0.f;
        if ((unsigned)j < (unsigned)IMG_H) {
            const float* row = xb + (size_t)j * IMG_W;
            v = *reinterpret_cast<const float2*>(row + wb);
            if (lane0 && has_l) lf = __ldg(row + (w0 - 1));
            if (lane31 && has_r) {
                const float2 t2 = *reinterpret_cast<const float2*>(row + (w0 + SW));
                rt1 = t2.x; rt2 = t2.y;
            }
        }
        float left  = __shfl_up_sync(0xffffffffu, v.y, 1);
        float right = __shfl_down_sync(0xffffffffu, v.x, 1);
        if (lane0)  left  = lf;
        if (lane31) right = rt1;

        const float hdx = left - v.y;
        const float hdy = v.x - right;
        const float hsx = fmaf(2.f, v.x, left + v.y);
        const float hsy = fmaf(2.f, v.y, v.x + right);
        const float hdR = v.y - rt2;              // col w0+SW (lane31 only)

        if (i >= 2) {
            const int m = r0 + i - 2;             // row with complete vertical window
            const float gyx  = hsP2x - hsx;
            const float gyy  = hsP2y - hsy;
            const float sgyx = fsign(gyx);
            const float sgyy = fsign(gyy);

            if (i <= RS + 1) {                    // emit y + y0 for rows r0..r0+RS-1
                const float gxx = fmaf(2.f, hdP1x, hdP2x + hdx);
                const float gxy = fmaf(2.f, hdP1y, hdP2y + hdy);
                const float gxR = fmaf(2.f, hdRP1, hdRP2 + hdR);

                *reinterpret_cast<float2*>(ybx + (size_t)m * IMG_W + wb) =
                    make_float2(gxx, gxy);
                *reinterpret_cast<float2*>(yby + (size_t)m * IMG_W + wb) =
                    make_float2(gyx, gyy);

                const float sgxx = fsign(gxx);
                const float sgxy = fsign(gxy);
                float sxn = __shfl_down_sync(0xffffffffu, sgxx, 1);
                if (lane31) sxn = fsign(gxR);

                if (m < IMG_H - 1) {
                    const size_t o = obase + (size_t)m * (IMG_W - 1) + wb;
                    y0[o] = sgxx - sgxy;
                    if (emit1) y0[o + 1] = sgxy - sxn;
                }
            }
            if (i >= 3) {
                const int m1 = m - 1;             // y1 row m1 needs sgy[m1], sgy[m1+1]
                if (m1 < IMG_H - 1) {
                    const size_t o = obase + (size_t)m1 * (IMG_W - 1) + wb;
                    y1[o] = sgyPx - sgyx;
                    if (emit1) y1[o + 1] = sgyPy - sgyy;
                }
            }
            sgyPx = sgyx; sgyPy = sgyy;
        }
        hdP2x = hdP1x; hdP1x = hdx;
        hdP2y = hdP1y; hdP1y = hdy;
        hsP2x = hsP1x; hsP1x = hsx;
        hsP2y = hsP1y; hsP1y = hsy;
        hdRP2 = hdRP1; hdRP1 = hdR;
    }
}

extern "C" void kernel_launch(void* const* d_in, const int* in_sizes, int n_in,
                              void* d_out, int out_size) {
    const float* x = (const float*)d_in[0];
    const int B = in_sizes[0] / (IMG_H * IMG_W);

    float* y  = (float*)d_out;
    float* y0 = y  + (size_t)B * 2 * IMG_H * IMG_W;
    float* y1 = y0 + (size_t)B * (IMG_H - 1) * (IMG_W - 1);

    dim3 block(NT, 1, 1);
    dim3 grid(IMG_W / SW, IMG_H / (RS * NWARP), B);
    sobel_sign_kernel<<<grid, block>>>(x, y, y0, y1);
}